// round 13
// baseline (speedup 1.0000x reference)
#include <cuda_runtime.h>

// SIMPLE k-subset sampler: exact log-ESP tree forward/backward + threefry-exact
// Gumbel top-down sampling. B = 65536 rows (8192 nodes x 8 ensemble), N = 32
// choices, k = 8, K = 9.
//
// Output layout: [ samples (2*8192*32*8 floats) | marginals (8192*32*8 floats) ]

#define NEGF (-10000000000.0f)

struct SubKeys { unsigned k[10]; };

__host__ __device__ __forceinline__ unsigned rotl32(unsigned x, int r) {
    return (x << r) | (x >> (32 - r));
}

// JAX threefry2x32: 20 rounds, 5 key injections.
__host__ __device__ __forceinline__ void threefry2x32(
    unsigned k0, unsigned k1, unsigned x0, unsigned x1,
    unsigned &o0, unsigned &o1)
{
    unsigned k2 = k0 ^ k1 ^ 0x1BD11BDAu;
    x0 += k0; x1 += k1;
#define TF_R(r) { x0 += x1; x1 = rotl32(x1, (r)); x1 ^= x0; }
    TF_R(13) TF_R(15) TF_R(26) TF_R(6)
    x0 += k1; x1 += k2 + 1u;
    TF_R(17) TF_R(29) TF_R(16) TF_R(24)
    x0 += k2; x1 += k0 + 2u;
    TF_R(13) TF_R(15) TF_R(26) TF_R(6)
    x0 += k0; x1 += k1 + 3u;
    TF_R(17) TF_R(29) TF_R(16) TF_R(24)
    x0 += k1; x1 += k2 + 4u;
    TF_R(13) TF_R(15) TF_R(26) TF_R(6)
    x0 += k2; x1 += k0 + 5u;
#undef TF_R
    o0 = x0; o1 = x1;
}

// Exactly JAX's uniform(tiny,1) -> gumbel path for float32.
__device__ __forceinline__ float gumbel_from_bits(unsigned bits) {
    const float TINY = __uint_as_float(0x00800000u);   // FLT_MIN (finfo.tiny)
    float f = __uint_as_float((bits >> 9) | 0x3F800000u) - 1.0f;  // [0,1), exact
    // floats * (maxval - minval) + minval ; (1.0f - TINY) rounds to 1.0f
    float u = f + TINY;
    u = fmaxf(TINY, u);
    return -logf(-logf(u));
}

// c[m] = logsumexp_j ( aL[j] + (m-j>=0 ? aR[m-j] : NEG) ), mirroring
// jax.nn.logsumexp: amax = max (init -inf, ascending j); sum exp ascending j.
__device__ __forceinline__ float conv_m(const float* __restrict__ aL,
                                        const float* __restrict__ aR, int m) {
    float t[9];
    float amax = __int_as_float(0xff800000);  // -inf
#pragma unroll
    for (int j = 0; j < 9; j++) {
        float ar = (m - j >= 0) ? aR[m - j] : NEGF;
        t[j] = aL[j] + ar;
        amax = fmaxf(amax, t[j]);
    }
    float s = 0.0f;
#pragma unroll
    for (int j = 0; j < 9; j++) s += expf(t[j] - amax);
    return logf(s) + amax;
}

// Level base offsets into the node table: base(l) = 64 - (64 >> l)
// l=0:0 (32 nodes), l=1:32 (16), l=2:48 (8), l=3:56 (4), l=4:60 (2), l=5:62 (1)

__global__ void __launch_bounds__(256)
simple_sampler_kernel(const float* __restrict__ scores,
                      float* __restrict__ out,
                      SubKeys keys)
{
    constexpr int WARPS = 8;
    __shared__ float s_lev[WARPS][63 * 9];   // all up-pass tables
    __shared__ float s_extA[WARPS][16 * 9];  // ext ping (<=16 nodes)
    __shared__ float s_extB[WARPS][32 * 9];  // ext pong (<=32 nodes; holds leaf ext)
    __shared__ int   s_cntA[WARPS][64];      // counts ping: [sample][node]
    __shared__ int   s_cntB[WARPS][64];      // counts pong

    const int w    = threadIdx.x >> 5;
    const int lane = threadIdx.x & 31;
    const int row  = blockIdx.x * WARPS + w;   // 0..65535
    const int node = row >> 3;                 // 0..8191
    const int e    = row & 7;                  // ensemble index

    float* lev = s_lev[w];

    // ---- leaf init: lev[i][0]=0, [1]=theta_i, rest NEG (lane = leaf i) ----
    const float th = scores[(node * 32 + lane) * 8 + e];
    {
        float* p = lev + lane * 9;
        p[0] = 0.0f;
        p[1] = th;
#pragma unroll
        for (int j = 2; j < 9; j++) p[j] = NEGF;
    }
    __syncwarp();

    // ---- up pass: 31 convolutions over 5 levels ----
    for (int l = 1; l <= 5; l++) {
        const int cb = 64 - (64 >> (l - 1));   // child base
        const int pb = 64 - (64 >> l);         // parent base
        const int tasks = (32 >> l) * 9;
        for (int t = lane; t < tasks; t += 32) {
            const int nd = t / 9, m = t - nd * 9;
            const float* aL = lev + (cb + 2 * nd) * 9;
            lev[(pb + nd) * 9 + m] = conv_m(aL, aL + 9, m);
        }
        __syncwarp();
    }
    const float logZ = lev[62 * 9 + 8];

    // ---- down pass: subtree-excluded ESP tables ----
    float* extP = s_extA[w];
    float* extC = s_extB[w];
    if (lane < 9) extP[lane] = (lane == 0) ? 0.0f : NEGF;
    __syncwarp();
    for (int l = 4; l >= 0; l--) {
        const int cb = 64 - (64 >> l);         // child-level base in lev
        const int tasks = (32 >> l) * 9;
        for (int t = lane; t < tasks; t += 32) {
            const int c = t / 9, m = t - c * 9;
            const float* sib = lev + (cb + (c ^ 1)) * 9;  // sibling table
            const float* ep  = extP + (c >> 1) * 9;       // parent ext
            extC[c * 9 + m] = conv_m(ep, sib, m);
        }
        __syncwarp();
        float* tmp = extP; extP = extC; extC = tmp;
    }
    // extP = leaf exts (32 nodes x 9). Note: 5 swaps -> extP points at s_extB.

    // ---- marginals: P(x_i=1 | sum=k) = exp(theta + ext[k-1] - logZ) ----
    const float marg = expf((th + extP[lane * 9 + 7]) - logZ);
    out[4194304 + ((node * 32 + lane) * 8 + e)] = marg;

    // ---- sampling: top-down Gumbel argmax, 2 samples ----
    int* cp = s_cntA[w];
    int* cc = s_cntB[w];
    if (lane < 2) cp[lane * 32] = 8;   // root count = k for both samples
    __syncwarp();

    for (int li = 0; li < 5; li++) {
        const int l = 4 - li;          // child level
        const int n = 16 >> l;         // number of (L,R) pairs this level
        const int cb = 64 - (64 >> l);
        const unsigned k0 = keys.k[2 * li], k1 = keys.k[2 * li + 1];
        const int tasks = 2 * n;       // (sample, pair)
        for (int t = lane; t < tasks; t += 32) {
            const int s = (t >= n) ? 1 : 0;
            const int p = t - s * n;
            const float* aL = lev + (cb + 2 * p) * 9;
            const float* aR = aL + 9;
            const int c = cp[s * 32 + p];
            // gumbel flat index: ((s*B + b)*n + p)*K + j, partitionable stream
            const unsigned gbase =
                ((unsigned)(s * 65536 + row) * (unsigned)n + (unsigned)p) * 9u;
            float best = 0.0f; int bi = 0;
#pragma unroll
            for (int j = 0; j < 9; j++) {
                const int idx = c - j;
                const float ar = (idx >= 0) ? aR[idx] : NEGF;
                const float lg = aL[j] + ar;
                unsigned o0, o1;
                threefry2x32(k0, k1, 0u, gbase + (unsigned)j, o0, o1);
                const float g = gumbel_from_bits(o0 ^ o1);
                const float v = lg + g;
                if (j == 0 || v > best) { best = v; bi = j; }
            }
            cc[s * 32 + 2 * p]     = bi;
            cc[s * 32 + 2 * p + 1] = c - bi;
        }
        __syncwarp();
        int* tmp = cp; cp = cc; cc = tmp;
    }

    // ---- write samples: (c - m) + m in fp32, matching the straight-through ----
#pragma unroll
    for (int s = 0; s < 2; s++) {
        const float cv = (float)cp[s * 32 + lane];
        const float sm = (cv - marg) + marg;
        out[((s * 8192 + node) * 32 + lane) * 8 + e] = sm;
    }
}

extern "C" void kernel_launch(void* const* d_in, const int* in_sizes, int n_in,
                              void* d_out, int out_size)
{
    const float* scores = (const float*)d_in[0];
    float* out = (float*)d_out;

    // Replicate: key = jax.random.key(42); 5x (key, sub) = split(key)
    // foldlike (threefry_partitionable default): keys[i] = tf(key, (0, i)).
    SubKeys ks;
    unsigned key0 = 0u, key1 = 42u;
    for (int i = 0; i < 5; i++) {
        unsigned a, b;
        threefry2x32(key0, key1, 0u, 1u, a, b);   // sub = keys[1]
        ks.k[2 * i] = a; ks.k[2 * i + 1] = b;
        threefry2x32(key0, key1, 0u, 0u, a, b);   // key = keys[0]
        key0 = a; key1 = b;
    }

    simple_sampler_kernel<<<8192, 256>>>(scores, out, ks);
}

// round 17
// speedup vs baseline: 1.0003x; 1.0003x over previous
#include <cuda_runtime.h>

// SIMPLE k-subset sampler: exact log-ESP tree forward/backward + threefry-exact
// Gumbel top-down sampling. B = 65536 rows (8192 nodes x 8 ensemble), N = 32
// choices, k = 8, K = 9.
//
// Output layout: [ samples (2*8192*32*8 floats) | marginals (8192*32*8 floats) ]

#define NEGF (-10000000000.0f)

struct SubKeys { unsigned k[10]; };

__host__ __device__ __forceinline__ unsigned rotl32(unsigned x, int r) {
    return (x << r) | (x >> (32 - r));
}

// JAX threefry2x32: 20 rounds, 5 key injections.
__host__ __device__ __forceinline__ void threefry2x32(
    unsigned k0, unsigned k1, unsigned x0, unsigned x1,
    unsigned &o0, unsigned &o1)
{
    unsigned k2 = k0 ^ k1 ^ 0x1BD11BDAu;
    x0 += k0; x1 += k1;
#define TF_R(r) { x0 += x1; x1 = rotl32(x1, (r)); x1 ^= x0; }
    TF_R(13) TF_R(15) TF_R(26) TF_R(6)
    x0 += k1; x1 += k2 + 1u;
    TF_R(17) TF_R(29) TF_R(16) TF_R(24)
    x0 += k2; x1 += k0 + 2u;
    TF_R(13) TF_R(15) TF_R(26) TF_R(6)
    x0 += k0; x1 += k1 + 3u;
    TF_R(17) TF_R(29) TF_R(16) TF_R(24)
    x0 += k1; x1 += k2 + 4u;
    TF_R(13) TF_R(15) TF_R(26) TF_R(6)
    x0 += k2; x1 += k0 + 5u;
#undef TF_R
    o0 = x0; o1 = x1;
}

// Exactly JAX's uniform(tiny,1) -> gumbel path for float32.
__device__ __forceinline__ float gumbel_from_bits(unsigned bits) {
    const float TINY = __uint_as_float(0x00800000u);   // FLT_MIN (finfo.tiny)
    float f = __uint_as_float((bits >> 9) | 0x3F800000u) - 1.0f;  // [0,1), exact
    // floats * (maxval - minval) + minval ; (1.0f - TINY) rounds to 1.0f
    float u = f + TINY;
    u = fmaxf(TINY, u);
    return -logf(-logf(u));
}

// c[m] = logsumexp_j ( aL[j] + (m-j>=0 ? aR[m-j] : NEG) ), mirroring
// jax.nn.logsumexp: amax = max (init -inf, ascending j); sum exp ascending j.
__device__ __forceinline__ float conv_m(const float* __restrict__ aL,
                                        const float* __restrict__ aR, int m) {
    float t[9];
    float amax = __int_as_float(0xff800000);  // -inf
#pragma unroll
    for (int j = 0; j < 9; j++) {
        float ar = (m - j >= 0) ? aR[m - j] : NEGF;
        t[j] = aL[j] + ar;
        amax = fmaxf(amax, t[j]);
    }
    float s = 0.0f;
#pragma unroll
    for (int j = 0; j < 9; j++) s += expf(t[j] - amax);
    return logf(s) + amax;
}

// Level base offsets into the node table: base(l) = 64 - (64 >> l)
// l=0:0 (32 nodes), l=1:32 (16), l=2:48 (8), l=3:56 (4), l=4:60 (2), l=5:62 (1)

__global__ void __launch_bounds__(256)
simple_sampler_kernel(const float* __restrict__ scores,
                      float* __restrict__ out,
                      SubKeys keys)
{
    constexpr int WARPS = 8;
    __shared__ float s_lev[WARPS][63 * 9];   // all up-pass tables
    __shared__ float s_extA[WARPS][16 * 9];  // ext ping (<=16 nodes)
    __shared__ float s_extB[WARPS][32 * 9];  // ext pong (<=32 nodes; holds leaf ext)
    __shared__ int   s_cntA[WARPS][64];      // counts ping: [sample][node]
    __shared__ int   s_cntB[WARPS][64];      // counts pong

    const int w    = threadIdx.x >> 5;
    const int lane = threadIdx.x & 31;
    const int row  = blockIdx.x * WARPS + w;   // 0..65535
    const int node = row >> 3;                 // 0..8191
    const int e    = row & 7;                  // ensemble index

    float* lev = s_lev[w];

    // ---- leaf init: lev[i][0]=0, [1]=theta_i, rest NEG (lane = leaf i) ----
    const float th = scores[(node * 32 + lane) * 8 + e];
    {
        float* p = lev + lane * 9;
        p[0] = 0.0f;
        p[1] = th;
#pragma unroll
        for (int j = 2; j < 9; j++) p[j] = NEGF;
    }
    __syncwarp();

    // ---- up pass: 31 convolutions over 5 levels ----
    for (int l = 1; l <= 5; l++) {
        const int cb = 64 - (64 >> (l - 1));   // child base
        const int pb = 64 - (64 >> l);         // parent base
        const int tasks = (32 >> l) * 9;
        for (int t = lane; t < tasks; t += 32) {
            const int nd = t / 9, m = t - nd * 9;
            const float* aL = lev + (cb + 2 * nd) * 9;
            lev[(pb + nd) * 9 + m] = conv_m(aL, aL + 9, m);
        }
        __syncwarp();
    }
    const float logZ = lev[62 * 9 + 8];

    // ---- down pass: subtree-excluded ESP tables ----
    float* extP = s_extA[w];
    float* extC = s_extB[w];
    if (lane < 9) extP[lane] = (lane == 0) ? 0.0f : NEGF;
    __syncwarp();
    for (int l = 4; l >= 0; l--) {
        const int cb = 64 - (64 >> l);         // child-level base in lev
        const int tasks = (32 >> l) * 9;
        for (int t = lane; t < tasks; t += 32) {
            const int c = t / 9, m = t - c * 9;
            const float* sib = lev + (cb + (c ^ 1)) * 9;  // sibling table
            const float* ep  = extP + (c >> 1) * 9;       // parent ext
            extC[c * 9 + m] = conv_m(ep, sib, m);
        }
        __syncwarp();
        float* tmp = extP; extP = extC; extC = tmp;
    }
    // extP = leaf exts (32 nodes x 9). Note: 5 swaps -> extP points at s_extB.

    // ---- marginals: P(x_i=1 | sum=k) = exp(theta + ext[k-1] - logZ) ----
    const float marg = expf((th + extP[lane * 9 + 7]) - logZ);
    out[4194304 + ((node * 32 + lane) * 8 + e)] = marg;

    // ---- sampling: top-down Gumbel argmax, 2 samples ----
    int* cp = s_cntA[w];
    int* cc = s_cntB[w];
    if (lane < 2) cp[lane * 32] = 8;   // root count = k for both samples
    __syncwarp();

    for (int li = 0; li < 5; li++) {
        const int l = 4 - li;          // child level
        const int n = 16 >> l;         // number of (L,R) pairs this level
        const int cb = 64 - (64 >> l);
        const unsigned k0 = keys.k[2 * li], k1 = keys.k[2 * li + 1];
        const int tasks = 2 * n;       // (sample, pair)
        for (int t = lane; t < tasks; t += 32) {
            const int s = (t >= n) ? 1 : 0;
            const int p = t - s * n;
            const float* aL = lev + (cb + 2 * p) * 9;
            const float* aR = aL + 9;
            const int c = cp[s * 32 + p];
            // gumbel flat index: ((s*B + b)*n + p)*K + j, partitionable stream
            const unsigned gbase =
                ((unsigned)(s * 65536 + row) * (unsigned)n + (unsigned)p) * 9u;
            float best = 0.0f; int bi = 0;
#pragma unroll
            for (int j = 0; j < 9; j++) {
                const int idx = c - j;
                const float ar = (idx >= 0) ? aR[idx] : NEGF;
                const float lg = aL[j] + ar;
                unsigned o0, o1;
                threefry2x32(k0, k1, 0u, gbase + (unsigned)j, o0, o1);
                const float g = gumbel_from_bits(o0 ^ o1);
                const float v = lg + g;
                if (j == 0 || v > best) { best = v; bi = j; }
            }
            cc[s * 32 + 2 * p]     = bi;
            cc[s * 32 + 2 * p + 1] = c - bi;
        }
        __syncwarp();
        int* tmp = cp; cp = cc; cc = tmp;
    }

    // ---- write samples: (c - m) + m in fp32, matching the straight-through ----
#pragma unroll
    for (int s = 0; s < 2; s++) {
        const float cv = (float)cp[s * 32 + lane];
        const float sm = (cv - marg) + marg;
        out[((s * 8192 + node) * 32 + lane) * 8 + e] = sm;
    }
}

extern "C" void kernel_launch(void* const* d_in, const int* in_sizes, int n_in,
                              void* d_out, int out_size)
{
    const float* scores = (const float*)d_in[0];
    float* out = (float*)d_out;

    // Replicate: key = jax.random.key(42); 5x (key, sub) = split(key)
    // foldlike (threefry_partitionable default): keys[i] = tf(key, (0, i)).
    SubKeys ks;
    unsigned key0 = 0u, key1 = 42u;
    for (int i = 0; i < 5; i++) {
        unsigned a, b;
        threefry2x32(key0, key1, 0u, 1u, a, b);   // sub = keys[1]
        ks.k[2 * i] = a; ks.k[2 * i + 1] = b;
        threefry2x32(key0, key1, 0u, 0u, a, b);   // key = keys[0]
        key0 = a; key1 = b;
    }

    simple_sampler_kernel<<<8192, 256>>>(scores, out, ks);
}